// round 4
// baseline (speedup 1.0000x reference)
#include <cuda_runtime.h>
#include <cuda_bf16.h>

#define D_MODEL 768
#define NTOK 4096           // B*S = 2*2048
#define SEQ 2048
#define NHEAD 12
#define HDIM 64
#define LORA_R 16
#define LORA_SCALE 4.0f     // U * alpha/sqrt(R) = 1.0 * 16/4

typedef unsigned long long ull;

// ---------------- packed fp32x2 helpers (exact IEEE fp32, 2x rate) ---------
__device__ __forceinline__ ull pk2(float lo, float hi) {
    ull r;
    asm("mov.b64 %0, {%1, %2};" : "=l"(r)
        : "r"(__float_as_uint(lo)), "r"(__float_as_uint(hi)));
    return r;
}
__device__ __forceinline__ void fma2(ull& d, ull a, ull b) {
    asm("fma.rn.f32x2 %0, %1, %2, %0;" : "+l"(d) : "l"(a), "l"(b));
}
__device__ __forceinline__ void mul2(ull& d, ull a, ull b) {
    asm("mul.rn.f32x2 %0, %1, %2;" : "=l"(d) : "l"(a), "l"(b));
}
__device__ __forceinline__ float2 upk2(ull v) {
    unsigned lo, hi;
    asm("mov.b64 {%0, %1}, %2;" : "=r"(lo), "=r"(hi) : "l"(v));
    return make_float2(__uint_as_float(lo), __uint_as_float(hi));
}
// single-instruction MUFU.EX2 (exp2f without fast-math is a slow SW path!)
__device__ __forceinline__ float fexp2(float x) {
    float r;
    asm("ex2.approx.ftz.f32 %0, %1;" : "=f"(r) : "f"(x));
    return r;
}

// ---------------- scratch (device globals: no allocation allowed) ----------
__device__ float g_Mq[D_MODEL * D_MODEL];
__device__ float g_Mk[D_MODEL * D_MODEL];
__device__ float g_Mv[D_MODEL * D_MODEL];
__device__ float g_Mo[D_MODEL * D_MODEL];
__device__ float g_q[NTOK * D_MODEL];
__device__ float g_k[NTOK * D_MODEL];
__device__ float g_v[NTOK * D_MODEL];
__device__ float g_ao[NTOK * D_MODEL];

// ---------------- build 2 effective weights per launch ---------------------
// M[i][j] = W[j][i] + s*<A[i],A[j]>
__global__ void build_weight2_kernel(const float* __restrict__ W0,
                                     const float* __restrict__ A0,
                                     float s0,
                                     const float* __restrict__ W1,
                                     const float* __restrict__ A1,
                                     float s1,
                                     float* __restrict__ M0,
                                     float* __restrict__ M1) {
    const float* W = blockIdx.y ? W1 : W0;
    const float* A = blockIdx.y ? A1 : A0;
    float* M = blockIdx.y ? M1 : M0;
    float scale = blockIdx.y ? s1 : s0;

    int idx = blockIdx.x * blockDim.x + threadIdx.x;
    if (idx >= D_MODEL * D_MODEL) return;
    int i = idx / D_MODEL;
    int j = idx - i * D_MODEL;
    float acc = W[j * D_MODEL + i];
    if (scale != 0.0f) {
        float s = 0.0f;
#pragma unroll
        for (int r = 0; r < LORA_R; r++)
            s += A[i * LORA_R + r] * A[j * LORA_R + r];
        acc += scale * s;
    }
    M[idx] = acc;
}

// ---------------- SGEMM: Y = X*Mw + bias. N=K=768, BM=BN=128, BK=16 --------
__global__ __launch_bounds__(256, 2) void sgemm_bias_kernel(
    const float* __restrict__ X, const float* __restrict__ Mw,
    const float* __restrict__ bias, float* __restrict__ Y) {
    const int N = D_MODEL, K = D_MODEL;
    __shared__ float As[2][16][128];   // [buf][k][m]
    __shared__ float Bs[2][16][128];   // [buf][k][n]

    int tid  = threadIdx.x;
    int brow = blockIdx.y * 128;
    int bcol = blockIdx.x * 128;
    int tr = tid >> 4;           // 0..15
    int tc = tid & 15;           // 0..15

    int am = tid >> 1;           // 0..127
    int ak = (tid & 1) * 8;      // 0 or 8
    int bk = tid >> 5;           // 0..7
    int bn = (tid & 31) * 4;     // 0..124

    const float* Xp  = X  + (size_t)(brow + am) * K + ak;
    const float* Bp0 = Mw + (size_t)bk * N + bcol + bn;
    const float* Bp1 = Mw + (size_t)(bk + 8) * N + bcol + bn;

    ull acc[8][4];
#pragma unroll
    for (int i = 0; i < 8; i++)
#pragma unroll
        for (int j = 0; j < 4; j++) acc[i][j] = 0ULL;

    float4 a0v = *reinterpret_cast<const float4*>(Xp);
    float4 a1v = *reinterpret_cast<const float4*>(Xp + 4);
    float4 b0v = *reinterpret_cast<const float4*>(Bp0);
    float4 b1v = *reinterpret_cast<const float4*>(Bp1);
    As[0][ak + 0][am] = a0v.x; As[0][ak + 1][am] = a0v.y;
    As[0][ak + 2][am] = a0v.z; As[0][ak + 3][am] = a0v.w;
    As[0][ak + 4][am] = a1v.x; As[0][ak + 5][am] = a1v.y;
    As[0][ak + 6][am] = a1v.z; As[0][ak + 7][am] = a1v.w;
    *reinterpret_cast<float4*>(&Bs[0][bk][bn])     = b0v;
    *reinterpret_cast<float4*>(&Bs[0][bk + 8][bn]) = b1v;
    __syncthreads();

    int buf = 0;
    for (int k0 = 0; k0 < K; k0 += 16) {
        bool has = (k0 + 16) < K;
        if (has) {
            a0v = *reinterpret_cast<const float4*>(Xp + k0 + 16);
            a1v = *reinterpret_cast<const float4*>(Xp + k0 + 20);
            b0v = *reinterpret_cast<const float4*>(Bp0 + (size_t)(k0 + 16) * N);
            b1v = *reinterpret_cast<const float4*>(Bp1 + (size_t)(k0 + 16) * N);
        }
#pragma unroll
        for (int kk = 0; kk < 16; kk++) {
            float4 af0 = *reinterpret_cast<const float4*>(&As[buf][kk][tr * 8]);
            float4 af1 = *reinterpret_cast<const float4*>(&As[buf][kk][tr * 8 + 4]);
            ulonglong2 bl = *reinterpret_cast<const ulonglong2*>(&Bs[buf][kk][tc * 8]);
            ulonglong2 bh = *reinterpret_cast<const ulonglong2*>(&Bs[buf][kk][tc * 8 + 4]);
            float afs[8] = {af0.x, af0.y, af0.z, af0.w, af1.x, af1.y, af1.z, af1.w};
#pragma unroll
            for (int i = 0; i < 8; i++) {
                ull da = pk2(afs[i], afs[i]);
                fma2(acc[i][0], da, bl.x);
                fma2(acc[i][1], da, bl.y);
                fma2(acc[i][2], da, bh.x);
                fma2(acc[i][3], da, bh.y);
            }
        }
        if (has) {
            As[buf ^ 1][ak + 0][am] = a0v.x; As[buf ^ 1][ak + 1][am] = a0v.y;
            As[buf ^ 1][ak + 2][am] = a0v.z; As[buf ^ 1][ak + 3][am] = a0v.w;
            As[buf ^ 1][ak + 4][am] = a1v.x; As[buf ^ 1][ak + 5][am] = a1v.y;
            As[buf ^ 1][ak + 6][am] = a1v.z; As[buf ^ 1][ak + 7][am] = a1v.w;
            *reinterpret_cast<float4*>(&Bs[buf ^ 1][bk][bn])     = b0v;
            *reinterpret_cast<float4*>(&Bs[buf ^ 1][bk + 8][bn]) = b1v;
        }
        __syncthreads();
        buf ^= 1;
    }

#pragma unroll
    for (int i = 0; i < 8; i++) {
        size_t row = brow + tr * 8 + i;
        int col = bcol + tc * 8;
        float2 p0 = upk2(acc[i][0]), p1 = upk2(acc[i][1]);
        float2 p2 = upk2(acc[i][2]), p3 = upk2(acc[i][3]);
        float4 o0, o1;
        o0.x = p0.x + bias[col + 0]; o0.y = p0.y + bias[col + 1];
        o0.z = p1.x + bias[col + 2]; o0.w = p1.y + bias[col + 3];
        o1.x = p2.x + bias[col + 4]; o1.y = p2.y + bias[col + 5];
        o1.z = p3.x + bias[col + 6]; o1.w = p3.y + bias[col + 7];
        *reinterpret_cast<float4*>(&Y[row * N + col])     = o0;
        *reinterpret_cast<float4*>(&Y[row * N + col + 4]) = o1;
    }
}

// ---------------- attention: flash-style, 64-query tiles -------------------
// Thread (lr, lc): owns output row lr, cols lc..lc+15 through the WHOLE tile.
#define KT_STRIDE 68
#define SS_STRIDE 68
#define ATT_SMEM ((4096 + 64 * KT_STRIDE + 4096 + 64 * SS_STRIDE) * 4)
#define QSCALE (0.125f * 1.4426950408889634f)   // 1/sqrt(64) * log2(e)

__global__ __launch_bounds__(256, 3) void attn_kernel(
    const float* __restrict__ q, const float* __restrict__ k,
    const float* __restrict__ v, float* __restrict__ o) {
    extern __shared__ float sm[];
    float* Qs = sm;                       // [64][64], pre-scaled by QSCALE
    float* Kt = sm + 4096;                // [d][key], stride 68
    float* Vs = Kt + 64 * KT_STRIDE;      // [64][64]
    float* Ss = Vs + 4096;                // [64][68]: exp'd probabilities p

    int qt = blockIdx.x;
    int bh = blockIdx.y;
    int b = bh / NHEAD;
    int h = bh - b * NHEAD;
    size_t base = (size_t)b * SEQ * D_MODEL + (size_t)h * HDIM;

    int tid = threadIdx.x;
    int lr = tid >> 2;               // 0..63: row
    int lc = (tid & 3) * 16;         // 0,16,32,48: col segment

    // load Q tile (fold softmax scale + log2e for ex2)
    {
        const float* src = q + base + (size_t)(qt * 64 + lr) * D_MODEL + lc;
        float4* dst = reinterpret_cast<float4*>(&Qs[lr * 64 + lc]);
#pragma unroll
        for (int i = 0; i < 4; i++) {
            float4 qv = reinterpret_cast<const float4*>(src)[i];
            qv.x *= QSCALE; qv.y *= QSCALE; qv.z *= QSCALE; qv.w *= QSCALE;
            dst[i] = qv;
        }
    }

    float m = -1e30f, l = 0.0f;
    ull oacc[8];
#pragma unroll
    for (int i = 0; i < 8; i++) oacc[i] = 0ULL;

    for (int kt0 = 0; kt0 < SEQ; kt0 += 64) {
        // load K (transposed into Kt) and V
        {
            const float* ksrc = k + base + (size_t)(kt0 + lr) * D_MODEL + lc;
            const float* vsrc = v + base + (size_t)(kt0 + lr) * D_MODEL + lc;
            float4* vdst = reinterpret_cast<float4*>(&Vs[lr * 64 + lc]);
#pragma unroll
            for (int i = 0; i < 4; i++) {
                float4 kv = reinterpret_cast<const float4*>(ksrc)[i];
                int c0 = lc + i * 4;
                Kt[(c0 + 0) * KT_STRIDE + lr] = kv.x;
                Kt[(c0 + 1) * KT_STRIDE + lr] = kv.y;
                Kt[(c0 + 2) * KT_STRIDE + lr] = kv.z;
                Kt[(c0 + 3) * KT_STRIDE + lr] = kv.w;
                vdst[i] = reinterpret_cast<const float4*>(vsrc)[i];
            }
        }
        __syncthreads();

        // scores for row lr, cols lc..lc+15, accumulated in registers
        ull sacc[8];
#pragma unroll
        for (int i = 0; i < 8; i++) sacc[i] = 0ULL;
#pragma unroll 2
        for (int d0 = 0; d0 < 64; d0 += 4) {
            float4 qv = *reinterpret_cast<const float4*>(&Qs[lr * 64 + d0]);
#pragma unroll
            for (int dd = 0; dd < 4; dd++) {
                float qa = (dd == 0) ? qv.x : (dd == 1) ? qv.y
                         : (dd == 2) ? qv.z : qv.w;
                ull qd = pk2(qa, qa);
                const ulonglong2* kp =
                    reinterpret_cast<const ulonglong2*>(&Kt[(d0 + dd) * KT_STRIDE + lc]);
                ulonglong2 k0 = kp[0];
                ulonglong2 k1 = kp[1];
                fma2(sacc[0], qd, k0.x);
                fma2(sacc[1], qd, k0.y);
                fma2(sacc[2], qd, k1.x);
                fma2(sacc[3], qd, k1.y);
                ulonglong2 k2 = kp[2];
                ulonglong2 k3 = kp[3];
                fma2(sacc[4], qd, k2.x);
                fma2(sacc[5], qd, k2.y);
                fma2(sacc[6], qd, k3.x);
                fma2(sacc[7], qd, k3.y);
            }
        }

        // register softmax (quad of 4 lanes covers the 64 cols of row lr)
        {
            float s[16];
#pragma unroll
            for (int i = 0; i < 8; i++) {
                float2 p = upk2(sacc[i]);
                s[2 * i] = p.x; s[2 * i + 1] = p.y;
            }
            float rmax = s[0];
#pragma unroll
            for (int i = 1; i < 16; i++) rmax = fmaxf(rmax, s[i]);
            rmax = fmaxf(rmax, __shfl_xor_sync(0xffffffffu, rmax, 1));
            rmax = fmaxf(rmax, __shfl_xor_sync(0xffffffffu, rmax, 2));
            float newm = fmaxf(m, rmax);
            float alpha = fexp2(m - newm);
            m = newm;
            float rsum = 0.0f;
#pragma unroll
            for (int i = 0; i < 16; i++) {
                s[i] = fexp2(s[i] - newm);
                rsum += s[i];
            }
            rsum += __shfl_xor_sync(0xffffffffu, rsum, 1);
            rsum += __shfl_xor_sync(0xffffffffu, rsum, 2);
            l = l * alpha + rsum;
            // store p (only consumed by this quad)
            float* prow = &Ss[lr * SS_STRIDE + lc];
#pragma unroll
            for (int i = 0; i < 4; i++) {
                float4 pv = make_float4(s[4 * i], s[4 * i + 1], s[4 * i + 2], s[4 * i + 3]);
                *reinterpret_cast<float4*>(&prow[4 * i]) = pv;
            }
            ull ad = pk2(alpha, alpha);
#pragma unroll
            for (int i = 0; i < 8; i++) mul2(oacc[i], oacc[i], ad);
        }
        __syncwarp();

        // PV: oacc[cols lc..lc+15] += p[lr][j] * V[j][cols]
        {
            const float* prow = &Ss[lr * SS_STRIDE];
#pragma unroll 4
            for (int j = 0; j < 64; j++) {
                float pj = prow[j];
                ull pd = pk2(pj, pj);
                const ulonglong2* vp =
                    reinterpret_cast<const ulonglong2*>(&Vs[j * 64 + lc]);
                ulonglong2 v0 = vp[0];
                ulonglong2 v1 = vp[1];
                fma2(oacc[0], pd, v0.x);
                fma2(oacc[1], pd, v0.y);
                fma2(oacc[2], pd, v1.x);
                fma2(oacc[3], pd, v1.y);
                ulonglong2 v2 = vp[2];
                ulonglong2 v3 = vp[3];
                fma2(oacc[4], pd, v2.x);
                fma2(oacc[5], pd, v2.y);
                fma2(oacc[6], pd, v3.x);
                fma2(oacc[7], pd, v3.y);
            }
        }
        __syncthreads();
    }

    float inv = 1.0f / l;
    float* dst = o + base + (size_t)(qt * 64 + lr) * D_MODEL + lc;
#pragma unroll
    for (int i = 0; i < 4; i++) {
        float2 p0 = upk2(oacc[2 * i + 0]);
        float2 p1 = upk2(oacc[2 * i + 1]);
        float4 ov = make_float4(p0.x * inv, p0.y * inv, p1.x * inv, p1.y * inv);
        reinterpret_cast<float4*>(dst)[i] = ov;
    }
}

// ---------------- launch ---------------------------------------------------
extern "C" void kernel_launch(void* const* d_in, const int* in_sizes, int n_in,
                              void* d_out, int out_size) {
    const float* query = (const float*)d_in[0];
    const float* key_  = (const float*)d_in[1];
    const float* value = (const float*)d_in[2];
    const float* Wq = (const float*)d_in[3];
    const float* bq = (const float*)d_in[4];
    const float* Aq = (const float*)d_in[5];
    const float* Wk = (const float*)d_in[6];
    const float* bk = (const float*)d_in[7];
    const float* Ak = (const float*)d_in[8];
    const float* Wv = (const float*)d_in[9];
    const float* bv = (const float*)d_in[10];
    const float* Av = (const float*)d_in[11];
    const float* Wo = (const float*)d_in[12];
    const float* bo = (const float*)d_in[13];
    float* out = (float*)d_out;

    float *pMq, *pMk, *pMv, *pMo, *pq, *pk, *pv, *pao;
    cudaGetSymbolAddress((void**)&pMq, g_Mq);
    cudaGetSymbolAddress((void**)&pMk, g_Mk);
    cudaGetSymbolAddress((void**)&pMv, g_Mv);
    cudaGetSymbolAddress((void**)&pMo, g_Mo);
    cudaGetSymbolAddress((void**)&pq, g_q);
    cudaGetSymbolAddress((void**)&pk, g_k);
    cudaGetSymbolAddress((void**)&pv, g_v);
    cudaGetSymbolAddress((void**)&pao, g_ao);

    cudaFuncSetAttribute(attn_kernel,
                         cudaFuncAttributeMaxDynamicSharedMemorySize, ATT_SMEM);

    int nw = D_MODEL * D_MODEL;
    dim3 bgrid((nw + 255) / 256, 2);
    // launches 0 and 1 (so attn below is launch index 5 for ncu -s 5 -c 1)
    build_weight2_kernel<<<bgrid, 256>>>(Wq, Aq, LORA_SCALE, Wk, Ak, LORA_SCALE,
                                         pMq, pMk);
    build_weight2_kernel<<<bgrid, 256>>>(Wv, Av, LORA_SCALE, Wo, Av, 0.0f,
                                         pMv, pMo);

    dim3 ggrid(D_MODEL / 128, NTOK / 128);   // (6, 32) — launches 2,3,4
    sgemm_bias_kernel<<<ggrid, 256>>>(query, pMq, bq, pq);
    sgemm_bias_kernel<<<ggrid, 256>>>(key_,  pMk, bk, pk);
    sgemm_bias_kernel<<<ggrid, 256>>>(value, pMv, bv, pv);

    dim3 agrid(SEQ / 64, 2 * NHEAD);         // (32, 24) — launch 5 (profiled)
    attn_kernel<<<agrid, 256, ATT_SMEM>>>(pq, pk, pv, pao);

    sgemm_bias_kernel<<<ggrid, 256>>>(pao, pMo, bo, out);
}

// round 5
// speedup vs baseline: 1.5665x; 1.5665x over previous
#include <cuda_runtime.h>
#include <cuda_bf16.h>

#define D_MODEL 768
#define NTOK 4096           // B*S = 2*2048
#define SEQ 2048
#define NHEAD 12
#define HDIM 64
#define LORA_R 16
#define LORA_SCALE 4.0f     // U * alpha/sqrt(R) = 1.0 * 16/4

typedef unsigned long long ull;

// ---------------- packed fp32x2 helpers (exact IEEE fp32, 2x rate) ---------
__device__ __forceinline__ ull pk2(float lo, float hi) {
    ull r;
    asm("mov.b64 %0, {%1, %2};" : "=l"(r)
        : "r"(__float_as_uint(lo)), "r"(__float_as_uint(hi)));
    return r;
}
__device__ __forceinline__ void fma2(ull& d, ull a, ull b) {
    asm("fma.rn.f32x2 %0, %1, %2, %0;" : "+l"(d) : "l"(a), "l"(b));
}
__device__ __forceinline__ void mul2(ull& d, ull a, ull b) {
    asm("mul.rn.f32x2 %0, %1, %2;" : "=l"(d) : "l"(a), "l"(b));
}
__device__ __forceinline__ float2 upk2(ull v) {
    unsigned lo, hi;
    asm("mov.b64 {%0, %1}, %2;" : "=r"(lo), "=r"(hi) : "l"(v));
    return make_float2(__uint_as_float(lo), __uint_as_float(hi));
}
__device__ __forceinline__ float fexp2(float x) {
    float r;
    asm("ex2.approx.ftz.f32 %0, %1;" : "=f"(r) : "f"(x));
    return r;
}

// ---------------- scratch (device globals: no allocation allowed) ----------
__device__ float g_Mq[D_MODEL * D_MODEL];
__device__ float g_Mk[D_MODEL * D_MODEL];
__device__ float g_Mv[D_MODEL * D_MODEL];
__device__ float g_Mo[D_MODEL * D_MODEL];
__device__ float g_q[NTOK * D_MODEL];
__device__ float g_k[NTOK * D_MODEL];
__device__ float g_v[NTOK * D_MODEL];
__device__ float g_ao[NTOK * D_MODEL];

// ---------------- build all 4 effective weights in ONE launch --------------
__global__ void build_weight4_kernel(const float* __restrict__ Wq,
                                     const float* __restrict__ Aq,
                                     const float* __restrict__ Wk,
                                     const float* __restrict__ Ak,
                                     const float* __restrict__ Wv,
                                     const float* __restrict__ Av,
                                     const float* __restrict__ Wo,
                                     float* __restrict__ Mq,
                                     float* __restrict__ Mk,
                                     float* __restrict__ Mv,
                                     float* __restrict__ Mo) {
    int which = blockIdx.y;
    const float* W = (which == 0) ? Wq : (which == 1) ? Wk : (which == 2) ? Wv : Wo;
    const float* A = (which == 0) ? Aq : (which == 1) ? Ak : Av;
    float* M = (which == 0) ? Mq : (which == 1) ? Mk : (which == 2) ? Mv : Mo;
    float scale = (which == 3) ? 0.0f : LORA_SCALE;

    int idx = blockIdx.x * blockDim.x + threadIdx.x;
    if (idx >= D_MODEL * D_MODEL) return;
    int i = idx / D_MODEL;
    int j = idx - i * D_MODEL;
    float acc = W[j * D_MODEL + i];
    if (scale != 0.0f) {
        float s = 0.0f;
#pragma unroll
        for (int r = 0; r < LORA_R; r++)
            s += A[i * LORA_R + r] * A[j * LORA_R + r];
        acc += scale * s;
    }
    M[idx] = acc;
}

// ---------------- no-op padding kernels (ncu launch-index alignment) -------
__global__ void nop_kernel() {}

// ---------------- SGEMM x3 (z-batched): Y = X*Mw + bias --------------------
__global__ __launch_bounds__(256, 2) void sgemm3_kernel(
    const float* __restrict__ X0, const float* __restrict__ X1, const float* __restrict__ X2,
    const float* __restrict__ M0, const float* __restrict__ M1, const float* __restrict__ M2,
    const float* __restrict__ B0, const float* __restrict__ B1, const float* __restrict__ B2,
    float* __restrict__ Y0, float* __restrict__ Y1, float* __restrict__ Y2) {
    const int N = D_MODEL, K = D_MODEL;
    int z = blockIdx.z;
    const float* X    = (z == 0) ? X0 : (z == 1) ? X1 : X2;
    const float* Mw   = (z == 0) ? M0 : (z == 1) ? M1 : M2;
    const float* bias = (z == 0) ? B0 : (z == 1) ? B1 : B2;
    float* Y          = (z == 0) ? Y0 : (z == 1) ? Y1 : Y2;

    __shared__ float As[2][16][128];   // [buf][k][m]
    __shared__ float Bs[2][16][128];   // [buf][k][n]

    int tid  = threadIdx.x;
    int brow = blockIdx.y * 128;
    int bcol = blockIdx.x * 128;
    int tr = tid >> 4;
    int tc = tid & 15;

    int am = tid >> 1;
    int ak = (tid & 1) * 8;
    int bk = tid >> 5;
    int bn = (tid & 31) * 4;

    const float* Xp  = X  + (size_t)(brow + am) * K + ak;
    const float* Bp0 = Mw + (size_t)bk * N + bcol + bn;
    const float* Bp1 = Mw + (size_t)(bk + 8) * N + bcol + bn;

    ull acc[8][4];
#pragma unroll
    for (int i = 0; i < 8; i++)
#pragma unroll
        for (int j = 0; j < 4; j++) acc[i][j] = 0ULL;

    float4 a0v = *reinterpret_cast<const float4*>(Xp);
    float4 a1v = *reinterpret_cast<const float4*>(Xp + 4);
    float4 b0v = *reinterpret_cast<const float4*>(Bp0);
    float4 b1v = *reinterpret_cast<const float4*>(Bp1);
    As[0][ak + 0][am] = a0v.x; As[0][ak + 1][am] = a0v.y;
    As[0][ak + 2][am] = a0v.z; As[0][ak + 3][am] = a0v.w;
    As[0][ak + 4][am] = a1v.x; As[0][ak + 5][am] = a1v.y;
    As[0][ak + 6][am] = a1v.z; As[0][ak + 7][am] = a1v.w;
    *reinterpret_cast<float4*>(&Bs[0][bk][bn])     = b0v;
    *reinterpret_cast<float4*>(&Bs[0][bk + 8][bn]) = b1v;
    __syncthreads();

    int buf = 0;
    for (int k0 = 0; k0 < K; k0 += 16) {
        bool has = (k0 + 16) < K;
        if (has) {
            a0v = *reinterpret_cast<const float4*>(Xp + k0 + 16);
            a1v = *reinterpret_cast<const float4*>(Xp + k0 + 20);
            b0v = *reinterpret_cast<const float4*>(Bp0 + (size_t)(k0 + 16) * N);
            b1v = *reinterpret_cast<const float4*>(Bp1 + (size_t)(k0 + 16) * N);
        }
#pragma unroll
        for (int kk = 0; kk < 16; kk++) {
            float4 af0 = *reinterpret_cast<const float4*>(&As[buf][kk][tr * 8]);
            float4 af1 = *reinterpret_cast<const float4*>(&As[buf][kk][tr * 8 + 4]);
            ulonglong2 bl = *reinterpret_cast<const ulonglong2*>(&Bs[buf][kk][tc * 8]);
            ulonglong2 bh = *reinterpret_cast<const ulonglong2*>(&Bs[buf][kk][tc * 8 + 4]);
            float afs[8] = {af0.x, af0.y, af0.z, af0.w, af1.x, af1.y, af1.z, af1.w};
#pragma unroll
            for (int i = 0; i < 8; i++) {
                ull da = pk2(afs[i], afs[i]);
                fma2(acc[i][0], da, bl.x);
                fma2(acc[i][1], da, bl.y);
                fma2(acc[i][2], da, bh.x);
                fma2(acc[i][3], da, bh.y);
            }
        }
        if (has) {
            As[buf ^ 1][ak + 0][am] = a0v.x; As[buf ^ 1][ak + 1][am] = a0v.y;
            As[buf ^ 1][ak + 2][am] = a0v.z; As[buf ^ 1][ak + 3][am] = a0v.w;
            As[buf ^ 1][ak + 4][am] = a1v.x; As[buf ^ 1][ak + 5][am] = a1v.y;
            As[buf ^ 1][ak + 6][am] = a1v.z; As[buf ^ 1][ak + 7][am] = a1v.w;
            *reinterpret_cast<float4*>(&Bs[buf ^ 1][bk][bn])     = b0v;
            *reinterpret_cast<float4*>(&Bs[buf ^ 1][bk + 8][bn]) = b1v;
        }
        __syncthreads();
        buf ^= 1;
    }

#pragma unroll
    for (int i = 0; i < 8; i++) {
        size_t row = brow + tr * 8 + i;
        int col = bcol + tc * 8;
        float2 p0 = upk2(acc[i][0]), p1 = upk2(acc[i][1]);
        float2 p2 = upk2(acc[i][2]), p3 = upk2(acc[i][3]);
        float4 o0, o1;
        o0.x = p0.x + bias[col + 0]; o0.y = p0.y + bias[col + 1];
        o0.z = p1.x + bias[col + 2]; o0.w = p1.y + bias[col + 3];
        o1.x = p2.x + bias[col + 4]; o1.y = p2.y + bias[col + 5];
        o1.z = p3.x + bias[col + 6]; o1.w = p3.y + bias[col + 7];
        *reinterpret_cast<float4*>(&Y[row * N + col])     = o0;
        *reinterpret_cast<float4*>(&Y[row * N + col + 4]) = o1;
    }
}

// ---------------- attention v2: packed-over-d scores, row-major K ----------
// Score phase: thread (sr = (tid>>4)*4 rows, tc = tid&15 -> cols {tc+16g}).
// Softmax/PV phase: thread (lr = tid>>2 row, lc = (tid&3)*16 col segment).
#define AST 68
#define ATT_SMEM (4 * 64 * AST * 4)
#define QSCALE (0.125f * 1.4426950408889634f)   // 1/sqrt(64) * log2(e)

__global__ __launch_bounds__(256, 2) void attn_kernel(
    const float* __restrict__ q, const float* __restrict__ k,
    const float* __restrict__ v, float* __restrict__ o) {
    extern __shared__ float sm[];
    float* Qs = sm;                 // [64][AST], pre-scaled by QSCALE
    float* Ks = sm + 64 * AST;      // [64][AST] row-major (key, d)
    float* Vs = Ks + 64 * AST;      // [64][AST] row-major (key, d)
    float* Ss = Vs + 64 * AST;      // [64][AST] scores -> probs

    int qt = blockIdx.x;
    int bh = blockIdx.y;
    int b = bh / NHEAD;
    int h = bh - b * NHEAD;
    size_t base = (size_t)b * SEQ * D_MODEL + (size_t)h * HDIM;

    int tid = threadIdx.x;
    int lr = tid >> 2;               // row (softmax/PV/load)
    int lc = (tid & 3) * 16;         // col segment
    int sr = (tid >> 4) * 4;         // score rows
    int tc = tid & 15;               // score col base (cols tc + 16g)

    // load Q tile (fold softmax scale + log2e)
    {
        const float* src = q + base + (size_t)(qt * 64 + lr) * D_MODEL + lc;
        float4* dst = reinterpret_cast<float4*>(&Qs[lr * AST + lc]);
#pragma unroll
        for (int i = 0; i < 4; i++) {
            float4 qv = reinterpret_cast<const float4*>(src)[i];
            qv.x *= QSCALE; qv.y *= QSCALE; qv.z *= QSCALE; qv.w *= QSCALE;
            dst[i] = qv;
        }
    }

    float m = -1e30f, l = 0.0f;
    ull oacc[8];
#pragma unroll
    for (int i = 0; i < 8; i++) oacc[i] = 0ULL;

    for (int kt0 = 0; kt0 < SEQ; kt0 += 64) {
        // load K and V row-major (no transpose)
        {
            const float* ksrc = k + base + (size_t)(kt0 + lr) * D_MODEL + lc;
            const float* vsrc = v + base + (size_t)(kt0 + lr) * D_MODEL + lc;
            float4* kdst = reinterpret_cast<float4*>(&Ks[lr * AST + lc]);
            float4* vdst = reinterpret_cast<float4*>(&Vs[lr * AST + lc]);
#pragma unroll
            for (int i = 0; i < 4; i++) {
                kdst[i] = reinterpret_cast<const float4*>(ksrc)[i];
                vdst[i] = reinterpret_cast<const float4*>(vsrc)[i];
            }
        }
        __syncthreads();

        // scores: 4 rows x 4 strided cols per thread, packed over d
        {
            ull sacc[4][4];
#pragma unroll
            for (int i = 0; i < 4; i++)
#pragma unroll
                for (int g = 0; g < 4; g++) sacc[i][g] = 0ULL;
#pragma unroll 2
            for (int d0 = 0; d0 < 64; d0 += 4) {
                ulonglong2 qp[4], kp[4];
#pragma unroll
                for (int i = 0; i < 4; i++)
                    qp[i] = *reinterpret_cast<const ulonglong2*>(&Qs[(sr + i) * AST + d0]);
#pragma unroll
                for (int g = 0; g < 4; g++)
                    kp[g] = *reinterpret_cast<const ulonglong2*>(&Ks[(tc + 16 * g) * AST + d0]);
#pragma unroll
                for (int i = 0; i < 4; i++)
#pragma unroll
                    for (int g = 0; g < 4; g++) {
                        fma2(sacc[i][g], qp[i].x, kp[g].x);
                        fma2(sacc[i][g], qp[i].y, kp[g].y);
                    }
            }
#pragma unroll
            for (int i = 0; i < 4; i++)
#pragma unroll
                for (int g = 0; g < 4; g++) {
                    float2 t = upk2(sacc[i][g]);
                    Ss[(sr + i) * AST + tc + 16 * g] = t.x + t.y;
                }
        }
        __syncthreads();

        // online softmax: quad covers the 64 cols of row lr
        {
            float* srow = &Ss[lr * AST + lc];
            float s[16];
#pragma unroll
            for (int i = 0; i < 4; i++) {
                float4 sv = *reinterpret_cast<const float4*>(&srow[4 * i]);
                s[4 * i] = sv.x; s[4 * i + 1] = sv.y;
                s[4 * i + 2] = sv.z; s[4 * i + 3] = sv.w;
            }
            float rmax = s[0];
#pragma unroll
            for (int i = 1; i < 16; i++) rmax = fmaxf(rmax, s[i]);
            rmax = fmaxf(rmax, __shfl_xor_sync(0xffffffffu, rmax, 1));
            rmax = fmaxf(rmax, __shfl_xor_sync(0xffffffffu, rmax, 2));
            float newm = fmaxf(m, rmax);
            float alpha = fexp2(m - newm);
            m = newm;
            float rsum = 0.0f;
#pragma unroll
            for (int i = 0; i < 16; i++) {
                s[i] = fexp2(s[i] - newm);
                rsum += s[i];
            }
            rsum += __shfl_xor_sync(0xffffffffu, rsum, 1);
            rsum += __shfl_xor_sync(0xffffffffu, rsum, 2);
            l = l * alpha + rsum;
#pragma unroll
            for (int i = 0; i < 4; i++) {
                float4 pv = make_float4(s[4 * i], s[4 * i + 1], s[4 * i + 2], s[4 * i + 3]);
                *reinterpret_cast<float4*>(&srow[4 * i]) = pv;
            }
            ull ad = pk2(alpha, alpha);
#pragma unroll
            for (int i = 0; i < 8; i++) mul2(oacc[i], oacc[i], ad);
        }
        __syncwarp();

        // PV: oacc[row lr][cols lc..lc+15] += p[lr][j] * V[j][cols]
        {
            const float* prow = &Ss[lr * AST];
#pragma unroll 4
            for (int j = 0; j < 64; j++) {
                float pj = prow[j];
                ull pd = pk2(pj, pj);
                const ulonglong2* vp =
                    reinterpret_cast<const ulonglong2*>(&Vs[j * AST + lc]);
                ulonglong2 v0 = vp[0];
                ulonglong2 v1 = vp[1];
                fma2(oacc[0], pd, v0.x);
                fma2(oacc[1], pd, v0.y);
                fma2(oacc[2], pd, v1.x);
                fma2(oacc[3], pd, v1.y);
                ulonglong2 v2 = vp[2];
                ulonglong2 v3 = vp[3];
                fma2(oacc[4], pd, v2.x);
                fma2(oacc[5], pd, v2.y);
                fma2(oacc[6], pd, v3.x);
                fma2(oacc[7], pd, v3.y);
            }
        }
        __syncthreads();
    }

    float inv = 1.0f / l;
    float* dst = o + base + (size_t)(qt * 64 + lr) * D_MODEL + lc;
#pragma unroll
    for (int i = 0; i < 4; i++) {
        float2 p0 = upk2(oacc[2 * i + 0]);
        float2 p1 = upk2(oacc[2 * i + 1]);
        float4 ov = make_float4(p0.x * inv, p0.y * inv, p1.x * inv, p1.y * inv);
        reinterpret_cast<float4*>(dst)[i] = ov;
    }
}

// ---------------- launch ---------------------------------------------------
extern "C" void kernel_launch(void* const* d_in, const int* in_sizes, int n_in,
                              void* d_out, int out_size) {
    const float* query = (const float*)d_in[0];
    const float* key_  = (const float*)d_in[1];
    const float* value = (const float*)d_in[2];
    const float* Wq = (const float*)d_in[3];
    const float* bq = (const float*)d_in[4];
    const float* Aq = (const float*)d_in[5];
    const float* Wk = (const float*)d_in[6];
    const float* bk = (const float*)d_in[7];
    const float* Ak = (const float*)d_in[8];
    const float* Wv = (const float*)d_in[9];
    const float* bv = (const float*)d_in[10];
    const float* Av = (const float*)d_in[11];
    const float* Wo = (const float*)d_in[12];
    const float* bo = (const float*)d_in[13];
    float* out = (float*)d_out;

    float *pMq, *pMk, *pMv, *pMo, *pq, *pk, *pv, *pao;
    cudaGetSymbolAddress((void**)&pMq, g_Mq);
    cudaGetSymbolAddress((void**)&pMk, g_Mk);
    cudaGetSymbolAddress((void**)&pMv, g_Mv);
    cudaGetSymbolAddress((void**)&pMo, g_Mo);
    cudaGetSymbolAddress((void**)&pq, g_q);
    cudaGetSymbolAddress((void**)&pk, g_k);
    cudaGetSymbolAddress((void**)&pv, g_v);
    cudaGetSymbolAddress((void**)&pao, g_ao);

    cudaFuncSetAttribute(attn_kernel,
                         cudaFuncAttributeMaxDynamicSharedMemorySize, ATT_SMEM);

    int nw = D_MODEL * D_MODEL;
    dim3 bgrid((nw + 255) / 256, 4);
    build_weight4_kernel<<<bgrid, 256>>>(Wq, Aq, Wk, Ak, Wv, Av, Wo,    // #0
                                         pMq, pMk, pMv, pMo);

    dim3 ggrid(D_MODEL / 128, NTOK / 128, 3);                           // #1
    sgemm3_kernel<<<ggrid, 256>>>(query, key_, value,
                                  pMq, pMk, pMv,
                                  bq, bk, bv,
                                  pq, pk, pv);

    nop_kernel<<<1, 32>>>();                                            // #2
    nop_kernel<<<1, 32>>>();                                            // #3

    dim3 agrid(SEQ / 64, 2 * NHEAD);                                    // #4
    attn_kernel<<<agrid, 256, ATT_SMEM>>>(pq, pk, pv, pao);

    dim3 ogrid(D_MODEL / 128, NTOK / 128, 1);                           // #5
    sgemm3_kernel<<<ogrid, 256>>>(pao, pao, pao,
                                  pMo, pMo, pMo,
                                  bo, bo, bo,
                                  out, out, out);
}